// round 10
// baseline (speedup 1.0000x reference)
#include <cuda_runtime.h>
#include <cuda_bf16.h>
#include <math.h>

// ---------------------------------------------------------------------------
// ann2_snn1 — bit-faithful emulation of the JAX/XLA-CPU reference (verified
// rel_err == 0.0). Numerics contract (must not change):
//  * every dot product: ONE f32 accumulator, strictly ascending k, __fmaf_rn
//    (zero-padded k-tails are exact)
//  * elementwise ops: separate f32 rounds in reference order
//  * logistic = 0.5 + 0.5*tanh(0.5x) with XLA's rational tanh
// ---------------------------------------------------------------------------

#define BATCH 1024
#define HID   500
#define NIN   784
#define NOUT  10
#define TLEN  100
#define THALF 50

__device__ float g_h[BATCH * HID];
__device__ float g_drive[BATCH * HID];
__device__ float g_cur[BATCH * TLEN * NOUT];   // [b][t][j] pre-bias dots

#define A1F ((float)1.1466802242428472)    // exp(-1/4)+exp(-1)
#define A2F ((float)-0.28650479686019009)  // -exp(-1/4)*exp(-1)
#define SGF ((float)0.77880078307140487)   // exp(-1/4)

__device__ __forceinline__ float xla_tanh_f32(float x)
{
    const float kMax = 7.90531110763549805f;
    float xc = fminf(fmaxf(x, -kMax), kMax);
    float x2 = __fmul_rn(xc, xc);
    float p = -2.76076847742355e-16f;
    p = __fadd_rn(__fmul_rn(p, x2), 2.00018790482477e-13f);
    p = __fadd_rn(__fmul_rn(p, x2), -8.60467152213735e-11f);
    p = __fadd_rn(__fmul_rn(p, x2), 5.12229709037114e-08f);
    p = __fadd_rn(__fmul_rn(p, x2), 1.48572235717979e-05f);
    p = __fadd_rn(__fmul_rn(p, x2), 6.37261928875436e-04f);
    p = __fadd_rn(__fmul_rn(p, x2), 4.89352455891786e-03f);
    float num = __fmul_rn(xc, p);
    float q = 1.19825839466702e-06f;
    q = __fadd_rn(__fmul_rn(q, x2), 1.18534705686654e-04f);
    q = __fadd_rn(__fmul_rn(q, x2), 2.26843463243900e-03f);
    q = __fadd_rn(__fmul_rn(q, x2), 4.89352518554385e-03f);
    float r = __fdiv_rn(num, q);
    return (fabsf(x) < 0.0004f) ? x : r;
}

__device__ __forceinline__ float xla_sigmoid(float x)
{
    float t = xla_tanh_f32(__fmul_rn(0.5f, x));
    return __fadd_rn(0.5f, __fmul_rn(0.5f, t));
}

// ---------------------------------------------------------------------------
// Double-buffered SGEMM: C[M,N] = act(A[M,K] @ W[N,K]^T + bias[N])
// BM=64, BN=32, BK=16, 256 threads, 2x4 micro-tile.
// 256 blocks x 2/SM -> single co-resident wave, 16 warps/SM.
// ---------------------------------------------------------------------------
#define BM 64
#define BN 32
#define BK 16
#define AS_LD 68
#define WS_LD 36

template<int ACT>
__global__ __launch_bounds__(256)
void gemm_bias_act(const float* __restrict__ A, const float* __restrict__ W,
                   const float* __restrict__ bias, float* __restrict__ C,
                   int M, int N, int K)
{
    __shared__ float As[2][BK][AS_LD];
    __shared__ float Ws[2][BK][WS_LD];

    const int tid = threadIdx.x;
    const int tx  = tid & 7;            // n dir: 8 x 4 = 32
    const int ty  = tid >> 3;           // m dir: 32 x 2 = 64
    const int bm  = blockIdx.y * BM;
    const int bn  = blockIdx.x * BN;

    // A loader: 256 threads, one float4 each: row tid>>2 (0..63), k lc4*4
    const int lrow = tid >> 2;
    const int lc4  = tid & 3;
    // W loader: first 128 threads, one float4 each: row tid>>2 (0..31)
    const bool wactive = (tid < 128);

    const int T = (K + BK - 1) / BK;

    float acc[2][4] = {};
    float4 pa, pw;

    auto loadA = [&](int kb) {
        int k = kb + lc4 * 4;
        const float* ap = A + (size_t)(bm + lrow) * K;
        float4 v;
        if (k + 3 < K) {
            v = *(const float4*)(ap + k);
        } else {
            v.x = (k + 0 < K) ? ap[k + 0] : 0.f;
            v.y = (k + 1 < K) ? ap[k + 1] : 0.f;
            v.z = (k + 2 < K) ? ap[k + 2] : 0.f;
            v.w = (k + 3 < K) ? ap[k + 3] : 0.f;
        }
        pa = v;
    };
    auto loadW = [&](int kb) {
        if (!wactive) return;
        int wr = bn + (tid >> 2);
        int k  = kb + lc4 * 4;
        float4 v = make_float4(0.f, 0.f, 0.f, 0.f);
        if (wr < N) {
            const float* wp = W + (size_t)wr * K;
            if (k + 3 < K) {
                v = *(const float4*)(wp + k);
            } else {
                v.x = (k + 0 < K) ? wp[k + 0] : 0.f;
                v.y = (k + 1 < K) ? wp[k + 1] : 0.f;
                v.z = (k + 2 < K) ? wp[k + 2] : 0.f;
                v.w = (k + 3 < K) ? wp[k + 3] : 0.f;
            }
        }
        pw = v;
    };
    auto stage = [&](int buf) {
        int ka = lc4 * 4;
        As[buf][ka + 0][lrow] = pa.x;
        As[buf][ka + 1][lrow] = pa.y;
        As[buf][ka + 2][lrow] = pa.z;
        As[buf][ka + 3][lrow] = pa.w;
        if (wactive) {
            int wr = tid >> 2;
            Ws[buf][ka + 0][wr] = pw.x;
            Ws[buf][ka + 1][wr] = pw.y;
            Ws[buf][ka + 2][wr] = pw.z;
            Ws[buf][ka + 3][wr] = pw.w;
        }
    };

    loadA(0);
    loadW(0);
    stage(0);
    __syncthreads();

    for (int it = 0; it < T; it++) {
        const int cur = it & 1;
        if (it + 1 < T) {
            loadA((it + 1) * BK);
            loadW((it + 1) * BK);
        }
        #pragma unroll
        for (int k = 0; k < BK; k++) {
            float2 a2 = *(const float2*)&As[cur][k][ty * 2];
            float4 w4 = *(const float4*)&Ws[cur][k][tx * 4];
            float a[2] = {a2.x, a2.y};
            float w[4] = {w4.x, w4.y, w4.z, w4.w};
            #pragma unroll
            for (int i = 0; i < 2; i++)
                #pragma unroll
                for (int j = 0; j < 4; j++)
                    acc[i][j] = __fmaf_rn(a[i], w[j], acc[i][j]);
        }
        if (it + 1 < T) stage(cur ^ 1);
        __syncthreads();
    }

    const int n0 = bn + tx * 4;
    if (n0 < N) {
        float bv0 = bias[n0 + 0], bv1 = bias[n0 + 1];
        float bv2 = bias[n0 + 2], bv3 = bias[n0 + 3];
        #pragma unroll
        for (int i = 0; i < 2; i++) {
            int m = bm + ty * 2 + i;
            float x0 = __fadd_rn(acc[i][0], bv0);
            float x1 = __fadd_rn(acc[i][1], bv1);
            float x2 = __fadd_rn(acc[i][2], bv2);
            float x3 = __fadd_rn(acc[i][3], bv3);
            if (ACT == 0) {
                x0 = fmaxf(x0, 0.f); x1 = fmaxf(x1, 0.f);
                x2 = fmaxf(x2, 0.f); x3 = fmaxf(x3, 0.f);
            } else {
                x0 = xla_sigmoid(x0); x1 = xla_sigmoid(x1);
                x2 = xla_sigmoid(x2); x3 = xla_sigmoid(x3);
            }
            *(float4*)&C[(size_t)m * N + n0] = make_float4(x0, x1, x2, x3);
        }
    }
}

// ---------------------------------------------------------------------------
// Scan kernel A: block = (b, t-half). 256 threads, smem = 50x500 psp (100KB)
// -> 2 blocks/SM. psp recurrence recomputed from t=0 (registers), only this
// half's 50 rows stored. Dots (strict ascending-k chains) write to g_cur.
// w3 read from gmem (L1-resident, 20KB shared by all blocks).
// ---------------------------------------------------------------------------
__global__ __launch_bounds__(256)
void scan_a_kernel(const float* __restrict__ w3, float* __restrict__ curg)
{
    extern __shared__ float sp[];          // [THALF][HID]

    const int b    = blockIdx.x >> 1;
    const int half = blockIdx.x & 1;
    const int tid  = threadIdx.x;
    const int tlo  = half * THALF;

    // phase 1: psp recurrence (full, from t=0), store only rows [tlo, tlo+50)
    if (tid < 250) {
        const int k0 = tid, k1 = tid + 250;
        float d0 = g_drive[(size_t)b * HID + k0];
        float d1 = g_drive[(size_t)b * HID + k1];
        float p1a = 0.f, p2a = 0.f, p1b = 0.f, p2b = 0.f;
        if (half == 0) {
            #pragma unroll 5
            for (int t = 0; t < THALF; t++) {
                float pa = __fadd_rn(__fadd_rn(__fmul_rn(A1F, p1a),
                                               __fmul_rn(A2F, p2a)), d0);
                float pb = __fadd_rn(__fadd_rn(__fmul_rn(A1F, p1b),
                                               __fmul_rn(A2F, p2b)), d1);
                sp[t * HID + k0] = pa;
                sp[t * HID + k1] = pb;
                p2a = p1a; p1a = pa;
                p2b = p1b; p1b = pb;
            }
        } else {
            #pragma unroll 5
            for (int t = 0; t < THALF; t++) {   // warm-up, no stores
                float pa = __fadd_rn(__fadd_rn(__fmul_rn(A1F, p1a),
                                               __fmul_rn(A2F, p2a)), d0);
                float pb = __fadd_rn(__fadd_rn(__fmul_rn(A1F, p1b),
                                               __fmul_rn(A2F, p2b)), d1);
                p2a = p1a; p1a = pa;
                p2b = p1b; p1b = pb;
            }
            #pragma unroll 5
            for (int t = 0; t < THALF; t++) {
                float pa = __fadd_rn(__fadd_rn(__fmul_rn(A1F, p1a),
                                               __fmul_rn(A2F, p2a)), d0);
                float pb = __fadd_rn(__fadd_rn(__fmul_rn(A1F, p1b),
                                               __fmul_rn(A2F, p2b)), d1);
                sp[t * HID + k0] = pa;
                sp[t * HID + k1] = pb;
                p2a = p1a; p1a = pa;
                p2b = p1b; p1b = pb;
            }
        }
    }
    __syncthreads();

    // phase 2: 250 threads = (t_local, j-pair); 2 ascending-k FMA chains each
    if (tid < 250) {
        const int tl = tid / 5;
        const int j0 = (tid % 5) * 2;
        const float* pr = sp + tl * HID;
        const float* wa = w3 + j0 * HID;
        const float* wb = wa + HID;
        float a0 = 0.f, a1 = 0.f;
        #pragma unroll 5
        for (int k = 0; k < HID; k += 4) {
            float4 pv = *(const float4*)(pr + k);
            float4 q0 = __ldg((const float4*)(wa + k));
            float4 q1 = __ldg((const float4*)(wb + k));
            a0 = __fmaf_rn(pv.x, q0.x, a0); a0 = __fmaf_rn(pv.y, q0.y, a0);
            a0 = __fmaf_rn(pv.z, q0.z, a0); a0 = __fmaf_rn(pv.w, q0.w, a0);
            a1 = __fmaf_rn(pv.x, q1.x, a1); a1 = __fmaf_rn(pv.y, q1.y, a1);
            a1 = __fmaf_rn(pv.z, q1.z, a1); a1 = __fmaf_rn(pv.w, q1.w, a1);
        }
        float* cg = curg + (size_t)b * (TLEN * NOUT) + (tlo + tl) * NOUT;
        cg[j0]     = a0;
        cg[j0 + 1] = a1;
    }
}

// ---------------------------------------------------------------------------
// Scan kernel B: LIF recurrence. One thread per (b, j); reads g_cur
// sequentially over t (prefetchable, v-chain is the only dependency),
// per-op f32 rounds in reference order; writes spikes to out[b][j][t].
// ---------------------------------------------------------------------------
__global__ __launch_bounds__(128)
void lif_b_kernel(const float* __restrict__ curg, const float* __restrict__ b3,
                  float* __restrict__ out)
{
    const int id = blockIdx.x * 128 + threadIdx.x;
    if (id >= BATCH * NOUT) return;
    const int b = id / NOUT;
    const int j = id - b * NOUT;

    const float bb = b3[j];
    const float* cg = curg + (size_t)b * (TLEN * NOUT) + j;
    float* op = out + (size_t)b * (NOUT * TLEN) + j * TLEN;

    float v = 0.f, s = 0.f;
    #pragma unroll 4
    for (int t = 0; t < TLEN; t++) {
        float cur = __fadd_rn(cg[t * NOUT], bb);
        float t1  = __fmul_rn(SGF, v);
        float t2  = __fmul_rn(t1, __fsub_rn(1.f, s));
        float vn  = __fadd_rn(t2, cur);
        s = (vn >= 1.f) ? 1.f : 0.f;
        v = vn;
        op[t] = s;
    }
}

#define SCANA_SMEM (THALF * HID * (int)sizeof(float))   // 100,000 B

extern "C" void kernel_launch(void* const* d_in, const int* in_sizes, int n_in,
                              void* d_out, int out_size)
{
    const float* inputs = (const float*)d_in[0];  // [1024, 784]
    const float* w1     = (const float*)d_in[1];  // [500, 784]
    const float* b1     = (const float*)d_in[2];  // [500]
    const float* w2     = (const float*)d_in[3];  // [500, 500]
    const float* b2     = (const float*)d_in[4];  // [500]
    const float* w3     = (const float*)d_in[5];  // [10, 500]
    const float* b3     = (const float*)d_in[6];  // [10]
    float* out          = (float*)d_out;          // [1024, 10, 100]

    float* h_buf;
    float* drive_buf;
    float* cur_buf;
    cudaGetSymbolAddress((void**)&h_buf, g_h);
    cudaGetSymbolAddress((void**)&drive_buf, g_drive);
    cudaGetSymbolAddress((void**)&cur_buf, g_cur);

    cudaFuncSetAttribute(scan_a_kernel,
                         cudaFuncAttributeMaxDynamicSharedMemorySize, SCANA_SMEM);

    dim3 blk(256);
    dim3 grd((HID + BN - 1) / BN, BATCH / BM);   // 16 x 16 = 256 blocks
    gemm_bias_act<0><<<grd, blk>>>(inputs, w1, b1, h_buf, BATCH, HID, NIN);
    gemm_bias_act<1><<<grd, blk>>>(h_buf, w2, b2, drive_buf, BATCH, HID, HID);
    scan_a_kernel<<<BATCH * 2, 256, SCANA_SMEM>>>(w3, cur_buf);
    lif_b_kernel<<<(BATCH * NOUT + 127) / 128, 128>>>(cur_buf, b3, out);
}

// round 11
// speedup vs baseline: 1.5415x; 1.5415x over previous
#include <cuda_runtime.h>
#include <cuda_bf16.h>
#include <math.h>

// ---------------------------------------------------------------------------
// ann2_snn1 — bit-faithful emulation of the JAX/XLA-CPU reference (verified
// rel_err == 0.0). Numerics contract (must not change):
//  * every dot product: ONE f32 accumulator, strictly ascending k, __fmaf_rn
//    (zero-padded k-tails are exact)
//  * elementwise ops: separate f32 rounds in reference order
//  * logistic = 0.5 + 0.5*tanh(0.5x) with XLA's rational tanh
// ---------------------------------------------------------------------------

#define BATCH 1024
#define HID   500
#define NIN   784
#define NOUT  10
#define TLEN  100

__device__ float g_h[BATCH * HID];
__device__ float g_drive[BATCH * HID];

#define A1F ((float)1.1466802242428472)    // exp(-1/4)+exp(-1)
#define A2F ((float)-0.28650479686019009)  // -exp(-1/4)*exp(-1)
#define SGF ((float)0.77880078307140487)   // exp(-1/4)

__device__ __forceinline__ float xla_tanh_f32(float x)
{
    const float kMax = 7.90531110763549805f;
    float xc = fminf(fmaxf(x, -kMax), kMax);
    float x2 = __fmul_rn(xc, xc);
    float p = -2.76076847742355e-16f;
    p = __fadd_rn(__fmul_rn(p, x2), 2.00018790482477e-13f);
    p = __fadd_rn(__fmul_rn(p, x2), -8.60467152213735e-11f);
    p = __fadd_rn(__fmul_rn(p, x2), 5.12229709037114e-08f);
    p = __fadd_rn(__fmul_rn(p, x2), 1.48572235717979e-05f);
    p = __fadd_rn(__fmul_rn(p, x2), 6.37261928875436e-04f);
    p = __fadd_rn(__fmul_rn(p, x2), 4.89352455891786e-03f);
    float num = __fmul_rn(xc, p);
    float q = 1.19825839466702e-06f;
    q = __fadd_rn(__fmul_rn(q, x2), 1.18534705686654e-04f);
    q = __fadd_rn(__fmul_rn(q, x2), 2.26843463243900e-03f);
    q = __fadd_rn(__fmul_rn(q, x2), 4.89352518554385e-03f);
    float r = __fdiv_rn(num, q);
    return (fabsf(x) < 0.0004f) ? x : r;
}

__device__ __forceinline__ float xla_sigmoid(float x)
{
    float t = xla_tanh_f32(__fmul_rn(0.5f, x));
    return __fadd_rn(0.5f, __fmul_rn(0.5f, t));
}

// ---------------------------------------------------------------------------
// Single-warp-block SGEMM: C[M,N] = act(A[M,K] @ W[N,K]^T + bias[N])
// BM=32, BN=16, BK=16, 32 threads, 4x4 micro-tile (tx=n-group 0..3,
// ty=m-group 0..7). No __syncthreads at all — one warp per block,
// __syncwarp only. Register-prefetch double buffering. Grid ~1024 blocks
// -> ~7 warps/SM with ~1% wave imbalance, zero barrier serialization.
// ---------------------------------------------------------------------------
#define BM 32
#define BN 16
#define BK 16
#define AS_LD 36
#define WS_LD 20

template<int ACT>
__global__ __launch_bounds__(32)
void gemm_bias_act(const float* __restrict__ A, const float* __restrict__ W,
                   const float* __restrict__ bias, float* __restrict__ C,
                   int M, int N, int K)
{
    __shared__ float As[2][BK][AS_LD];
    __shared__ float Ws[2][BK][WS_LD];

    const int tid = threadIdx.x;
    const int tx  = tid & 3;            // n-group: cols tx*4..+3
    const int ty  = tid >> 2;           // m-group: rows ty*4..+3 (0..7)
    const int bm  = blockIdx.y * BM;
    const int bn  = blockIdx.x * BN;

    // loader mapping: lane -> (row = pass*8 + (tid>>2), k4 = tid&3)
    const int lr  = tid >> 2;           // 0..7
    const int lk4 = tid & 3;            // 0..3

    const int T = (K + BK - 1) / BK;

    float acc[4][4] = {};
    float4 pa[4], pw[2];

    auto loadA = [&](int kb) {
        int k = kb + lk4 * 4;
        #pragma unroll
        for (int p = 0; p < 4; p++) {
            const float* ap = A + (size_t)(bm + p * 8 + lr) * K;
            float4 v;
            if (k + 3 < K) {
                v = *(const float4*)(ap + k);
            } else {
                v.x = (k + 0 < K) ? ap[k + 0] : 0.f;
                v.y = (k + 1 < K) ? ap[k + 1] : 0.f;
                v.z = (k + 2 < K) ? ap[k + 2] : 0.f;
                v.w = (k + 3 < K) ? ap[k + 3] : 0.f;
            }
            pa[p] = v;
        }
    };
    auto loadW = [&](int kb) {
        int k = kb + lk4 * 4;
        #pragma unroll
        for (int q = 0; q < 2; q++) {
            int row = bn + q * 8 + lr;
            float4 v = make_float4(0.f, 0.f, 0.f, 0.f);
            if (row < N) {
                const float* wp = W + (size_t)row * K;
                if (k + 3 < K) {
                    v = *(const float4*)(wp + k);
                } else {
                    v.x = (k + 0 < K) ? wp[k + 0] : 0.f;
                    v.y = (k + 1 < K) ? wp[k + 1] : 0.f;
                    v.z = (k + 2 < K) ? wp[k + 2] : 0.f;
                    v.w = (k + 3 < K) ? wp[k + 3] : 0.f;
                }
            }
            pw[q] = v;
        }
    };
    auto stage = [&](int buf) {
        int ka = lk4 * 4;
        #pragma unroll
        for (int p = 0; p < 4; p++) {
            int row = p * 8 + lr;
            As[buf][ka + 0][row] = pa[p].x;
            As[buf][ka + 1][row] = pa[p].y;
            As[buf][ka + 2][row] = pa[p].z;
            As[buf][ka + 3][row] = pa[p].w;
        }
        #pragma unroll
        for (int q = 0; q < 2; q++) {
            int row = q * 8 + lr;
            Ws[buf][ka + 0][row] = pw[q].x;
            Ws[buf][ka + 1][row] = pw[q].y;
            Ws[buf][ka + 2][row] = pw[q].z;
            Ws[buf][ka + 3][row] = pw[q].w;
        }
    };

    loadA(0);
    loadW(0);
    stage(0);
    __syncwarp();

    for (int it = 0; it < T; it++) {
        const int cur = it & 1;
        if (it + 1 < T) {
            loadA((it + 1) * BK);
            loadW((it + 1) * BK);
        }
        #pragma unroll
        for (int k = 0; k < BK; k++) {
            float4 a4 = *(const float4*)&As[cur][k][ty * 4];
            float4 w4 = *(const float4*)&Ws[cur][k][tx * 4];
            float a[4] = {a4.x, a4.y, a4.z, a4.w};
            float w[4] = {w4.x, w4.y, w4.z, w4.w};
            #pragma unroll
            for (int i = 0; i < 4; i++)
                #pragma unroll
                for (int j = 0; j < 4; j++)
                    acc[i][j] = __fmaf_rn(a[i], w[j], acc[i][j]);
        }
        __syncwarp();
        if (it + 1 < T) {
            stage(cur ^ 1);
            __syncwarp();
        }
    }

    // epilogue: bias (separate f32 add) + activation, float4 stores
    const int n0 = bn + tx * 4;
    if (n0 < N) {        // n0 multiple of 4, N multiple of 4 -> n0+3 < N
        float bv0 = bias[n0 + 0], bv1 = bias[n0 + 1];
        float bv2 = bias[n0 + 2], bv3 = bias[n0 + 3];
        #pragma unroll
        for (int i = 0; i < 4; i++) {
            int m = bm + ty * 4 + i;
            float x0 = __fadd_rn(acc[i][0], bv0);
            float x1 = __fadd_rn(acc[i][1], bv1);
            float x2 = __fadd_rn(acc[i][2], bv2);
            float x3 = __fadd_rn(acc[i][3], bv3);
            if (ACT == 0) {
                x0 = fmaxf(x0, 0.f); x1 = fmaxf(x1, 0.f);
                x2 = fmaxf(x2, 0.f); x3 = fmaxf(x3, 0.f);
            } else {
                x0 = xla_sigmoid(x0); x1 = xla_sigmoid(x1);
                x2 = xla_sigmoid(x2); x3 = xla_sigmoid(x3);
            }
            *(float4*)&C[(size_t)m * N + n0] = make_float4(x0, x1, x2, x3);
        }
    }
}

// ---------------------------------------------------------------------------
// Scan kernel (R6 — measured best): one block (256 threads) per batch element.
// ---------------------------------------------------------------------------
__global__ __launch_bounds__(256)
void scan_kernel(const float* __restrict__ w3g, const float* __restrict__ b3,
                 float* __restrict__ out)
{
    extern __shared__ float sm[];
    float* sp = sm;                    // [TLEN][HID]  psp  (200,000 B)
    float* sw = sm + TLEN * HID;       // [NOUT][HID]  w3   ( 20,000 B)
    float* sc = sw + NOUT * HID;       // [TLEN][NOUT] dots (  4,000 B)

    const int b   = blockIdx.x;
    const int tid = threadIdx.x;

    // load w3 (coalesced float4)
    {
        const float4* src = (const float4*)w3g;
        float4* dst = (float4*)sw;
        for (int i = tid; i < (NOUT * HID) / 4; i += 256) dst[i] = src[i];
    }

    // phase 1: psp recurrence, 2 columns per thread
    if (tid < 250) {
        const int k0 = tid, k1 = tid + 250;
        float d0 = g_drive[(size_t)b * HID + k0];
        float d1 = g_drive[(size_t)b * HID + k1];
        float p1a = 0.f, p2a = 0.f, p1b = 0.f, p2b = 0.f;
        #pragma unroll 4
        for (int t = 0; t < TLEN; t++) {
            float pa = __fadd_rn(__fadd_rn(__fmul_rn(A1F, p1a),
                                           __fmul_rn(A2F, p2a)), d0);
            float pb = __fadd_rn(__fadd_rn(__fmul_rn(A1F, p1b),
                                           __fmul_rn(A2F, p2b)), d1);
            sp[t * HID + k0] = pa;
            sp[t * HID + k1] = pb;
            p2a = p1a; p1a = pa;
            p2b = p1b; p1b = pb;
        }
    }
    __syncthreads();

    // phase 2: thread = t, 5 j-accumulators, warp-uniform j-group
    {
        const int jg = tid >> 7;           // 0 (warps 0-3) or 1 (warps 4-7)
        const int t  = tid & 127;
        if (t < TLEN) {
            const float* pr = sp + t * HID;
            const float* wb = sw + jg * 5 * HID;
            float a0 = 0.f, a1 = 0.f, a2 = 0.f, a3 = 0.f, a4 = 0.f;
            #pragma unroll 5
            for (int k = 0; k < HID; k += 4) {
                float4 pv = *(const float4*)(pr + k);
                float4 q0 = *(const float4*)(wb + 0 * HID + k);
                float4 q1 = *(const float4*)(wb + 1 * HID + k);
                float4 q2 = *(const float4*)(wb + 2 * HID + k);
                float4 q3 = *(const float4*)(wb + 3 * HID + k);
                float4 q4 = *(const float4*)(wb + 4 * HID + k);
                a0 = __fmaf_rn(pv.x, q0.x, a0); a0 = __fmaf_rn(pv.y, q0.y, a0);
                a0 = __fmaf_rn(pv.z, q0.z, a0); a0 = __fmaf_rn(pv.w, q0.w, a0);
                a1 = __fmaf_rn(pv.x, q1.x, a1); a1 = __fmaf_rn(pv.y, q1.y, a1);
                a1 = __fmaf_rn(pv.z, q1.z, a1); a1 = __fmaf_rn(pv.w, q1.w, a1);
                a2 = __fmaf_rn(pv.x, q2.x, a2); a2 = __fmaf_rn(pv.y, q2.y, a2);
                a2 = __fmaf_rn(pv.z, q2.z, a2); a2 = __fmaf_rn(pv.w, q2.w, a2);
                a3 = __fmaf_rn(pv.x, q3.x, a3); a3 = __fmaf_rn(pv.y, q3.y, a3);
                a3 = __fmaf_rn(pv.z, q3.z, a3); a3 = __fmaf_rn(pv.w, q3.w, a3);
                a4 = __fmaf_rn(pv.x, q4.x, a4); a4 = __fmaf_rn(pv.y, q4.y, a4);
                a4 = __fmaf_rn(pv.z, q4.z, a4); a4 = __fmaf_rn(pv.w, q4.w, a4);
            }
            float* scr = sc + t * NOUT + jg * 5;
            scr[0] = a0; scr[1] = a1; scr[2] = a2; scr[3] = a3; scr[4] = a4;
        }
    }
    __syncthreads();

    // phase 3: LIF recurrence (exact reference op order); spikes -> sp region
    if (tid < NOUT) {
        float bb = b3[tid];
        float v = 0.f, s = 0.f;
        float* spk = sp + tid * TLEN;
        for (int t = 0; t < TLEN; t++) {
            float cur = __fadd_rn(sc[t * NOUT + tid], bb);
            float t1  = __fmul_rn(SGF, v);
            float t2  = __fmul_rn(t1, __fsub_rn(1.f, s));
            float vn  = __fadd_rn(t2, cur);
            s = (vn >= 1.f) ? 1.f : 0.f;
            v = vn;
            spk[t] = s;
        }
    }
    __syncthreads();

    float* ob = out + (size_t)b * (NOUT * TLEN);
    for (int i = tid; i < NOUT * TLEN; i += 256) ob[i] = sp[i];
}

#define SCAN_SMEM ((TLEN * HID + NOUT * HID + TLEN * NOUT) * (int)sizeof(float))

extern "C" void kernel_launch(void* const* d_in, const int* in_sizes, int n_in,
                              void* d_out, int out_size)
{
    const float* inputs = (const float*)d_in[0];  // [1024, 784]
    const float* w1     = (const float*)d_in[1];  // [500, 784]
    const float* b1     = (const float*)d_in[2];  // [500]
    const float* w2     = (const float*)d_in[3];  // [500, 500]
    const float* b2     = (const float*)d_in[4];  // [500]
    const float* w3     = (const float*)d_in[5];  // [10, 500]
    const float* b3     = (const float*)d_in[6];  // [10]
    float* out          = (float*)d_out;          // [1024, 10, 100]

    float* h_buf;
    float* drive_buf;
    cudaGetSymbolAddress((void**)&h_buf, g_h);
    cudaGetSymbolAddress((void**)&drive_buf, g_drive);

    cudaFuncSetAttribute(scan_kernel,
                         cudaFuncAttributeMaxDynamicSharedMemorySize, SCAN_SMEM);

    dim3 blk(32);
    dim3 grd((HID + BN - 1) / BN, BATCH / BM);   // 32 x 32 = 1024 blocks
    gemm_bias_act<0><<<grd, blk>>>(inputs, w1, b1, h_buf, BATCH, HID, NIN);
    gemm_bias_act<1><<<grd, blk>>>(h_buf, w2, b2, drive_buf, BATCH, HID, HID);
    scan_kernel<<<BATCH, 256, SCAN_SMEM>>>(w3, b3, out);
}

// round 12
// speedup vs baseline: 1.5862x; 1.0290x over previous
#include <cuda_runtime.h>
#include <cuda_bf16.h>
#include <math.h>

// ---------------------------------------------------------------------------
// ann2_snn1 — bit-faithful emulation of the JAX/XLA-CPU reference (verified
// rel_err == 0.0). Numerics contract (must not change):
//  * every dot product: ONE f32 accumulator, strictly ascending k, __fmaf_rn
//    (zero-padded k-tails are exact)
//  * elementwise ops: separate f32 rounds in reference order
//  * logistic = 0.5 + 0.5*tanh(0.5x) with XLA's rational tanh
// ---------------------------------------------------------------------------

#define BATCH 1024
#define HID   500
#define NIN   784
#define NOUT  10
#define TLEN  100

__device__ float g_h[BATCH * HID];
__device__ float g_drive[BATCH * HID];

#define A1F ((float)1.1466802242428472)    // exp(-1/4)+exp(-1)
#define A2F ((float)-0.28650479686019009)  // -exp(-1/4)*exp(-1)
#define SGF ((float)0.77880078307140487)   // exp(-1/4)

__device__ __forceinline__ float xla_tanh_f32(float x)
{
    const float kMax = 7.90531110763549805f;
    float xc = fminf(fmaxf(x, -kMax), kMax);
    float x2 = __fmul_rn(xc, xc);
    float p = -2.76076847742355e-16f;
    p = __fadd_rn(__fmul_rn(p, x2), 2.00018790482477e-13f);
    p = __fadd_rn(__fmul_rn(p, x2), -8.60467152213735e-11f);
    p = __fadd_rn(__fmul_rn(p, x2), 5.12229709037114e-08f);
    p = __fadd_rn(__fmul_rn(p, x2), 1.48572235717979e-05f);
    p = __fadd_rn(__fmul_rn(p, x2), 6.37261928875436e-04f);
    p = __fadd_rn(__fmul_rn(p, x2), 4.89352455891786e-03f);
    float num = __fmul_rn(xc, p);
    float q = 1.19825839466702e-06f;
    q = __fadd_rn(__fmul_rn(q, x2), 1.18534705686654e-04f);
    q = __fadd_rn(__fmul_rn(q, x2), 2.26843463243900e-03f);
    q = __fadd_rn(__fmul_rn(q, x2), 4.89352518554385e-03f);
    float r = __fdiv_rn(num, q);
    return (fabsf(x) < 0.0004f) ? x : r;
}

__device__ __forceinline__ float xla_sigmoid(float x)
{
    float t = xla_tanh_f32(__fmul_rn(0.5f, x));
    return __fadd_rn(0.5f, __fmul_rn(0.5f, t));
}

// ---------------------------------------------------------------------------
// Double-buffered SGEMM, BK=32 (half the barriers of BK=16):
// C[M,N] = act(A[M,K] @ W[N,K]^T + bias[N])
// BM=64, BN=32, 128 threads, 4x4 micro-tile, register-prefetch double buffer.
// A loader: 4 float4/thread; W loader: 2 float4/thread.
// ---------------------------------------------------------------------------
#define BM 64
#define BN 32
#define BK 32
#define AS_LD 68
#define WS_LD 36

template<int ACT>
__global__ __launch_bounds__(128)
void gemm_bias_act(const float* __restrict__ A, const float* __restrict__ W,
                   const float* __restrict__ bias, float* __restrict__ C,
                   int M, int N, int K)
{
    __shared__ float As[2][BK][AS_LD];
    __shared__ float Ws[2][BK][WS_LD];

    const int tid = threadIdx.x;
    const int tx  = tid & 7;            // n dir: 8 x 4 = 32
    const int ty  = tid >> 3;           // m dir: 16 x 4 = 64
    const int bm  = blockIdx.y * BM;
    const int bn  = blockIdx.x * BN;

    const int T = (K + BK - 1) / BK;

    float acc[4][4] = {};
    float4 pa[4], pw[2];

    // A tile: 64 rows x 8 float4-cols = 512 slots; 4 per thread
    auto loadA = [&](int kb) {
        #pragma unroll
        for (int p = 0; p < 4; p++) {
            int pos  = tid + p * 128;
            int row  = pos >> 3;            // 0..63
            int k    = kb + (pos & 7) * 4;
            const float* ap = A + (size_t)(bm + row) * K;
            float4 v;
            if (k + 3 < K) {
                v = *(const float4*)(ap + k);
            } else {
                v.x = (k + 0 < K) ? ap[k + 0] : 0.f;
                v.y = (k + 1 < K) ? ap[k + 1] : 0.f;
                v.z = (k + 2 < K) ? ap[k + 2] : 0.f;
                v.w = (k + 3 < K) ? ap[k + 3] : 0.f;
            }
            pa[p] = v;
        }
    };
    // W tile: 32 rows x 8 float4-cols = 256 slots; 2 per thread
    auto loadW = [&](int kb) {
        #pragma unroll
        for (int q = 0; q < 2; q++) {
            int pos = tid + q * 128;
            int row = pos >> 3;             // 0..31
            int k   = kb + (pos & 7) * 4;
            float4 v = make_float4(0.f, 0.f, 0.f, 0.f);
            int wr = bn + row;
            if (wr < N) {
                const float* wp = W + (size_t)wr * K;
                if (k + 3 < K) {
                    v = *(const float4*)(wp + k);
                } else {
                    v.x = (k + 0 < K) ? wp[k + 0] : 0.f;
                    v.y = (k + 1 < K) ? wp[k + 1] : 0.f;
                    v.z = (k + 2 < K) ? wp[k + 2] : 0.f;
                    v.w = (k + 3 < K) ? wp[k + 3] : 0.f;
                }
            }
            pw[q] = v;
        }
    };
    auto stage = [&](int buf) {
        #pragma unroll
        for (int p = 0; p < 4; p++) {
            int pos = tid + p * 128;
            int row = pos >> 3;
            int ka  = (pos & 7) * 4;
            As[buf][ka + 0][row] = pa[p].x;
            As[buf][ka + 1][row] = pa[p].y;
            As[buf][ka + 2][row] = pa[p].z;
            As[buf][ka + 3][row] = pa[p].w;
        }
        #pragma unroll
        for (int q = 0; q < 2; q++) {
            int pos = tid + q * 128;
            int row = pos >> 3;
            int kw  = (pos & 7) * 4;
            Ws[buf][kw + 0][row] = pw[q].x;
            Ws[buf][kw + 1][row] = pw[q].y;
            Ws[buf][kw + 2][row] = pw[q].z;
            Ws[buf][kw + 3][row] = pw[q].w;
        }
    };

    loadA(0);
    loadW(0);
    stage(0);
    __syncthreads();

    for (int it = 0; it < T; it++) {
        const int cur = it & 1;
        if (it + 1 < T) {
            loadA((it + 1) * BK);
            loadW((it + 1) * BK);
        }
        #pragma unroll
        for (int k = 0; k < BK; k++) {
            float4 a4 = *(const float4*)&As[cur][k][ty * 4];
            float4 w4 = *(const float4*)&Ws[cur][k][tx * 4];
            float a[4] = {a4.x, a4.y, a4.z, a4.w};
            float w[4] = {w4.x, w4.y, w4.z, w4.w};
            #pragma unroll
            for (int i = 0; i < 4; i++)
                #pragma unroll
                for (int j = 0; j < 4; j++)
                    acc[i][j] = __fmaf_rn(a[i], w[j], acc[i][j]);
        }
        if (it + 1 < T) stage(cur ^ 1);
        __syncthreads();
    }

    // epilogue: bias (separate f32 add) + activation, float4 stores
    const int n0 = bn + tx * 4;
    if (n0 < N) {
        float bv0 = bias[n0 + 0], bv1 = bias[n0 + 1];
        float bv2 = bias[n0 + 2], bv3 = bias[n0 + 3];
        #pragma unroll
        for (int i = 0; i < 4; i++) {
            int m = bm + ty * 4 + i;
            float x0 = __fadd_rn(acc[i][0], bv0);
            float x1 = __fadd_rn(acc[i][1], bv1);
            float x2 = __fadd_rn(acc[i][2], bv2);
            float x3 = __fadd_rn(acc[i][3], bv3);
            if (ACT == 0) {
                x0 = fmaxf(x0, 0.f); x1 = fmaxf(x1, 0.f);
                x2 = fmaxf(x2, 0.f); x3 = fmaxf(x3, 0.f);
            } else {
                x0 = xla_sigmoid(x0); x1 = xla_sigmoid(x1);
                x2 = xla_sigmoid(x2); x3 = xla_sigmoid(x3);
            }
            *(float4*)&C[(size_t)m * N + n0] = make_float4(x0, x1, x2, x3);
        }
    }
}

// ---------------------------------------------------------------------------
// Scan kernel (R6 — measured best): one block (256 threads) per batch element.
// ---------------------------------------------------------------------------
__global__ __launch_bounds__(256)
void scan_kernel(const float* __restrict__ w3g, const float* __restrict__ b3,
                 float* __restrict__ out)
{
    extern __shared__ float sm[];
    float* sp = sm;                    // [TLEN][HID]  psp  (200,000 B)
    float* sw = sm + TLEN * HID;       // [NOUT][HID]  w3   ( 20,000 B)
    float* sc = sw + NOUT * HID;       // [TLEN][NOUT] dots (  4,000 B)

    const int b   = blockIdx.x;
    const int tid = threadIdx.x;

    // load w3 (coalesced float4)
    {
        const float4* src = (const float4*)w3g;
        float4* dst = (float4*)sw;
        for (int i = tid; i < (NOUT * HID) / 4; i += 256) dst[i] = src[i];
    }

    // phase 1: psp recurrence, 2 columns per thread
    if (tid < 250) {
        const int k0 = tid, k1 = tid + 250;
        float d0 = g_drive[(size_t)b * HID + k0];
        float d1 = g_drive[(size_t)b * HID + k1];
        float p1a = 0.f, p2a = 0.f, p1b = 0.f, p2b = 0.f;
        #pragma unroll 4
        for (int t = 0; t < TLEN; t++) {
            float pa = __fadd_rn(__fadd_rn(__fmul_rn(A1F, p1a),
                                           __fmul_rn(A2F, p2a)), d0);
            float pb = __fadd_rn(__fadd_rn(__fmul_rn(A1F, p1b),
                                           __fmul_rn(A2F, p2b)), d1);
            sp[t * HID + k0] = pa;
            sp[t * HID + k1] = pb;
            p2a = p1a; p1a = pa;
            p2b = p1b; p1b = pb;
        }
    }
    __syncthreads();

    // phase 2: thread = t, 5 j-accumulators, warp-uniform j-group
    {
        const int jg = tid >> 7;           // 0 (warps 0-3) or 1 (warps 4-7)
        const int t  = tid & 127;
        if (t < TLEN) {
            const float* pr = sp + t * HID;
            const float* wb = sw + jg * 5 * HID;
            float a0 = 0.f, a1 = 0.f, a2 = 0.f, a3 = 0.f, a4 = 0.f;
            #pragma unroll 5
            for (int k = 0; k < HID; k += 4) {
                float4 pv = *(const float4*)(pr + k);
                float4 q0 = *(const float4*)(wb + 0 * HID + k);
                float4 q1 = *(const float4*)(wb + 1 * HID + k);
                float4 q2 = *(const float4*)(wb + 2 * HID + k);
                float4 q3 = *(const float4*)(wb + 3 * HID + k);
                float4 q4 = *(const float4*)(wb + 4 * HID + k);
                a0 = __fmaf_rn(pv.x, q0.x, a0); a0 = __fmaf_rn(pv.y, q0.y, a0);
                a0 = __fmaf_rn(pv.z, q0.z, a0); a0 = __fmaf_rn(pv.w, q0.w, a0);
                a1 = __fmaf_rn(pv.x, q1.x, a1); a1 = __fmaf_rn(pv.y, q1.y, a1);
                a1 = __fmaf_rn(pv.z, q1.z, a1); a1 = __fmaf_rn(pv.w, q1.w, a1);
                a2 = __fmaf_rn(pv.x, q2.x, a2); a2 = __fmaf_rn(pv.y, q2.y, a2);
                a2 = __fmaf_rn(pv.z, q2.z, a2); a2 = __fmaf_rn(pv.w, q2.w, a2);
                a3 = __fmaf_rn(pv.x, q3.x, a3); a3 = __fmaf_rn(pv.y, q3.y, a3);
                a3 = __fmaf_rn(pv.z, q3.z, a3); a3 = __fmaf_rn(pv.w, q3.w, a3);
                a4 = __fmaf_rn(pv.x, q4.x, a4); a4 = __fmaf_rn(pv.y, q4.y, a4);
                a4 = __fmaf_rn(pv.z, q4.z, a4); a4 = __fmaf_rn(pv.w, q4.w, a4);
            }
            float* scr = sc + t * NOUT + jg * 5;
            scr[0] = a0; scr[1] = a1; scr[2] = a2; scr[3] = a3; scr[4] = a4;
        }
    }
    __syncthreads();

    // phase 3: LIF recurrence (exact reference op order); spikes -> sp region
    if (tid < NOUT) {
        float bb = b3[tid];
        float v = 0.f, s = 0.f;
        float* spk = sp + tid * TLEN;
        for (int t = 0; t < TLEN; t++) {
            float cur = __fadd_rn(sc[t * NOUT + tid], bb);
            float t1  = __fmul_rn(SGF, v);
            float t2  = __fmul_rn(t1, __fsub_rn(1.f, s));
            float vn  = __fadd_rn(t2, cur);
            s = (vn >= 1.f) ? 1.f : 0.f;
            v = vn;
            spk[t] = s;
        }
    }
    __syncthreads();

    float* ob = out + (size_t)b * (NOUT * TLEN);
    for (int i = tid; i < NOUT * TLEN; i += 256) ob[i] = sp[i];
}

#define SCAN_SMEM ((TLEN * HID + NOUT * HID + TLEN * NOUT) * (int)sizeof(float))

extern "C" void kernel_launch(void* const* d_in, const int* in_sizes, int n_in,
                              void* d_out, int out_size)
{
    const float* inputs = (const float*)d_in[0];  // [1024, 784]
    const float* w1     = (const float*)d_in[1];  // [500, 784]
    const float* b1     = (const float*)d_in[2];  // [500]
    const float* w2     = (const float*)d_in[3];  // [500, 500]
    const float* b2     = (const float*)d_in[4];  // [500]
    const float* w3     = (const float*)d_in[5];  // [10, 500]
    const float* b3     = (const float*)d_in[6];  // [10]
    float* out          = (float*)d_out;          // [1024, 10, 100]

    float* h_buf;
    float* drive_buf;
    cudaGetSymbolAddress((void**)&h_buf, g_h);
    cudaGetSymbolAddress((void**)&drive_buf, g_drive);

    cudaFuncSetAttribute(scan_kernel,
                         cudaFuncAttributeMaxDynamicSharedMemorySize, SCAN_SMEM);

    dim3 blk(128);
    dim3 grd((HID + BN - 1) / BN, BATCH / BM);   // 16 x 16 = 256 blocks
    gemm_bias_act<0><<<grd, blk>>>(inputs, w1, b1, h_buf, BATCH, HID, NIN);
    gemm_bias_act<1><<<grd, blk>>>(h_buf, w2, b2, drive_buf, BATCH, HID, HID);
    scan_kernel<<<BATCH, 256, SCAN_SMEM>>>(w3, b3, out);
}

// round 14
// speedup vs baseline: 1.7143x; 1.0808x over previous
#include <cuda_runtime.h>
#include <cuda_bf16.h>
#include <cstdint>
#include <math.h>

// ---------------------------------------------------------------------------
// ann2_snn1 — bit-faithful emulation of the JAX/XLA-CPU reference (verified
// rel_err == 0.0). Numerics contract (must not change):
//  * every dot product: ONE f32 accumulator, strictly ascending k, __fmaf_rn
//    (zero-padded k-tails are exact)
//  * elementwise ops: separate f32 rounds in reference order
//  * logistic = 0.5 + 0.5*tanh(0.5x) with XLA's rational tanh
// ---------------------------------------------------------------------------

#define BATCH 1024
#define HID   500
#define NIN   784
#define NOUT  10
#define TLEN  100

__device__ float g_h[BATCH * HID];
__device__ float g_drive[BATCH * HID];

#define A1F ((float)1.1466802242428472)    // exp(-1/4)+exp(-1)
#define A2F ((float)-0.28650479686019009)  // -exp(-1/4)*exp(-1)
#define SGF ((float)0.77880078307140487)   // exp(-1/4)

__device__ __forceinline__ float xla_tanh_f32(float x)
{
    const float kMax = 7.90531110763549805f;
    float xc = fminf(fmaxf(x, -kMax), kMax);
    float x2 = __fmul_rn(xc, xc);
    float p = -2.76076847742355e-16f;
    p = __fadd_rn(__fmul_rn(p, x2), 2.00018790482477e-13f);
    p = __fadd_rn(__fmul_rn(p, x2), -8.60467152213735e-11f);
    p = __fadd_rn(__fmul_rn(p, x2), 5.12229709037114e-08f);
    p = __fadd_rn(__fmul_rn(p, x2), 1.48572235717979e-05f);
    p = __fadd_rn(__fmul_rn(p, x2), 6.37261928875436e-04f);
    p = __fadd_rn(__fmul_rn(p, x2), 4.89352455891786e-03f);
    float num = __fmul_rn(xc, p);
    float q = 1.19825839466702e-06f;
    q = __fadd_rn(__fmul_rn(q, x2), 1.18534705686654e-04f);
    q = __fadd_rn(__fmul_rn(q, x2), 2.26843463243900e-03f);
    q = __fadd_rn(__fmul_rn(q, x2), 4.89352518554385e-03f);
    float r = __fdiv_rn(num, q);
    return (fabsf(x) < 0.0004f) ? x : r;
}

__device__ __forceinline__ float xla_sigmoid(float x)
{
    float t = xla_tanh_f32(__fmul_rn(0.5f, x));
    return __fadd_rn(0.5f, __fmul_rn(0.5f, t));
}

// ---- cp.async helpers ----
__device__ __forceinline__ void cp_async16(unsigned int smem_dst,
                                           const void* gsrc, int src_bytes)
{
    asm volatile("cp.async.cg.shared.global [%0], [%1], 16, %2;"
                 :: "r"(smem_dst), "l"(gsrc), "r"(src_bytes));
}
__device__ __forceinline__ void cp_commit()
{
    asm volatile("cp.async.commit_group;");
}
template<int N>
__device__ __forceinline__ void cp_wait()
{
    asm volatile("cp.async.wait_group %0;" :: "n"(N));
}

// ---------------------------------------------------------------------------
// cp.async 4-stage pipelined SGEMM: C[M,N] = act(A[M,K] @ W[N,K]^T + bias[N])
// BM=64, BN=32, BK=16, 128 threads, 4x4 micro-tile.
// Smem tiles in gmem layout (k-contiguous rows) with chunk-XOR swizzle:
//   A: row stride 16 floats, chunk pos = c ^ ((m>>2)&3)   (conflict-free)
//   W: row stride 20 floats, chunk pos = c ^ ((n>>3)&3)   (conflict-free)
// Compute reads 4-k float4 fragments; accumulation is kk-ascending -> strict
// ascending-k single-accumulator chains. K-tail / N-guard via cp.async
// src_size zero-fill (exact: fma with 0 keeps acc bits).
// ---------------------------------------------------------------------------
#define BM 64
#define BN 32
#define BK 16
#define NSTAGE 4
#define A_STRIDE 16
#define W_STRIDE 20
#define A_TILE (BM * A_STRIDE)    // 1024 floats
#define W_TILE (BN * W_STRIDE)    // 640 floats

template<int ACT>
__global__ __launch_bounds__(128)
void gemm_bias_act(const float* __restrict__ A, const float* __restrict__ W,
                   const float* __restrict__ bias, float* __restrict__ C,
                   int M, int N, int K)
{
    __shared__ float As[NSTAGE][A_TILE];
    __shared__ float Ws[NSTAGE][W_TILE];

    const int tid = threadIdx.x;
    const int tx  = tid & 7;            // n dir: 8 x 4 = 32
    const int ty  = tid >> 3;           // m dir: 16 x 4 = 64
    const int bm  = blockIdx.y * BM;
    const int bn  = blockIdx.x * BN;

    const int T = (K + BK - 1) / BK;

    // ---- async loaders ----
    // A: 64 rows x 4 chunks = 256 chunks; 2 per thread (idx = tid, tid+128)
    // W: 32 rows x 4 chunks = 128 chunks; 1 per thread
    auto issue_stage = [&](int it) {
        const int s  = it & (NSTAGE - 1);
        const int kb = it * BK;
        unsigned int abase = (unsigned int)__cvta_generic_to_shared(&As[s][0]);
        unsigned int wbase = (unsigned int)__cvta_generic_to_shared(&Ws[s][0]);
        #pragma unroll
        for (int p = 0; p < 2; p++) {
            int idx = tid + p * 128;
            int m   = idx >> 2;
            int c   = idx & 3;
            int k0  = kb + c * 4;
            int rem = K - k0;
            int bytes = rem >= 4 ? 16 : (rem > 0 ? rem * 4 : 0);
            const float* src = A + (size_t)(bm + m) * K + (bytes ? k0 : 0);
            unsigned int dst = abase +
                (unsigned int)((m * A_STRIDE + ((c ^ ((m >> 2) & 3)) * 4)) * 4);
            cp_async16(dst, src, bytes);
        }
        {
            int n   = tid >> 2;
            int c   = tid & 3;
            int k0  = kb + c * 4;
            int wr  = bn + n;
            int rem = K - k0;
            int bytes = (wr < N) ? (rem >= 4 ? 16 : (rem > 0 ? rem * 4 : 0)) : 0;
            const float* src = W + (bytes ? ((size_t)wr * K + k0) : 0);
            unsigned int dst = wbase +
                (unsigned int)((n * W_STRIDE + ((c ^ ((n >> 3) & 3)) * 4)) * 4);
            cp_async16(dst, src, bytes);
        }
        cp_commit();
    };

    float acc[4][4] = {};

    // prologue: 3 stages in flight
    issue_stage(0);
    if (T > 1) issue_stage(1);
    if (T > 2) issue_stage(2);

    const int asw = ty & 3;          // A swizzle key: (m>>2)&3 == ty&3 for m=4ty+i
    const int wsw = (tx >> 1) & 3;   // W swizzle key: (n>>3)&3 for n=4tx+j

    for (int it = 0; it < T; it++) {
        const int s = it & (NSTAGE - 1);
        if (it + 3 < T) issue_stage(it + 3);
        cp_wait<3>();
        __syncthreads();

        #pragma unroll
        for (int c = 0; c < 4; c++) {
            float4 a4[4], w4[4];
            const int ac = (c ^ asw) * 4;
            const int wc = (c ^ wsw) * 4;
            #pragma unroll
            for (int i = 0; i < 4; i++)
                a4[i] = *(const float4*)&As[s][(ty * 4 + i) * A_STRIDE + ac];
            #pragma unroll
            for (int j = 0; j < 4; j++)
                w4[j] = *(const float4*)&Ws[s][(tx * 4 + j) * W_STRIDE + wc];
            #pragma unroll
            for (int kk = 0; kk < 4; kk++) {
                float a[4] = { kk == 0 ? a4[0].x : kk == 1 ? a4[0].y : kk == 2 ? a4[0].z : a4[0].w,
                               kk == 0 ? a4[1].x : kk == 1 ? a4[1].y : kk == 2 ? a4[1].z : a4[1].w,
                               kk == 0 ? a4[2].x : kk == 1 ? a4[2].y : kk == 2 ? a4[2].z : a4[2].w,
                               kk == 0 ? a4[3].x : kk == 1 ? a4[3].y : kk == 2 ? a4[3].z : a4[3].w };
                float w[4] = { kk == 0 ? w4[0].x : kk == 1 ? w4[0].y : kk == 2 ? w4[0].z : w4[0].w,
                               kk == 0 ? w4[1].x : kk == 1 ? w4[1].y : kk == 2 ? w4[1].z : w4[1].w,
                               kk == 0 ? w4[2].x : kk == 1 ? w4[2].y : kk == 2 ? w4[2].z : w4[2].w,
                               kk == 0 ? w4[3].x : kk == 1 ? w4[3].y : kk == 2 ? w4[3].z : w4[3].w };
                #pragma unroll
                for (int i = 0; i < 4; i++)
                    #pragma unroll
                    for (int j = 0; j < 4; j++)
                        acc[i][j] = __fmaf_rn(a[i], w[j], acc[i][j]);
            }
        }
        __syncthreads();
    }

    // epilogue: bias (separate f32 add) + activation, float4 stores
    const int n0 = bn + tx * 4;
    if (n0 < N) {
        float bv0 = bias[n0 + 0], bv1 = bias[n0 + 1];
        float bv2 = bias[n0 + 2], bv3 = bias[n0 + 3];
        #pragma unroll
        for (int i = 0; i < 4; i++) {
            int m = bm + ty * 4 + i;
            float x0 = __fadd_rn(acc[i][0], bv0);
            float x1 = __fadd_rn(acc[i][1], bv1);
            float x2 = __fadd_rn(acc[i][2], bv2);
            float x3 = __fadd_rn(acc[i][3], bv3);
            if (ACT == 0) {
                x0 = fmaxf(x0, 0.f); x1 = fmaxf(x1, 0.f);
                x2 = fmaxf(x2, 0.f); x3 = fmaxf(x3, 0.f);
            } else {
                x0 = xla_sigmoid(x0); x1 = xla_sigmoid(x1);
                x2 = xla_sigmoid(x2); x3 = xla_sigmoid(x3);
            }
            *(float4*)&C[(size_t)m * N + n0] = make_float4(x0, x1, x2, x3);
        }
    }
}

// ---------------------------------------------------------------------------
// Scan kernel (R6 — measured best): one block (256 threads) per batch element.
// ---------------------------------------------------------------------------
__global__ __launch_bounds__(256)
void scan_kernel(const float* __restrict__ w3g, const float* __restrict__ b3,
                 float* __restrict__ out)
{
    extern __shared__ float sm[];
    float* sp = sm;                    // [TLEN][HID]  psp  (200,000 B)
    float* sw = sm + TLEN * HID;       // [NOUT][HID]  w3   ( 20,000 B)
    float* sc = sw + NOUT * HID;       // [TLEN][NOUT] dots (  4,000 B)

    const int b   = blockIdx.x;
    const int tid = threadIdx.x;

    {
        const float4* src = (const float4*)w3g;
        float4* dst = (float4*)sw;
        for (int i = tid; i < (NOUT * HID) / 4; i += 256) dst[i] = src[i];
    }

    if (tid < 250) {
        const int k0 = tid, k1 = tid + 250;
        float d0 = g_drive[(size_t)b * HID + k0];
        float d1 = g_drive[(size_t)b * HID + k1];
        float p1a = 0.f, p2a = 0.f, p1b = 0.f, p2b = 0.f;
        #pragma unroll 4
        for (int t = 0; t < TLEN; t++) {
            float pa = __fadd_rn(__fadd_rn(__fmul_rn(A1F, p1a),
                                           __fmul_rn(A2F, p2a)), d0);
            float pb = __fadd_rn(__fadd_rn(__fmul_rn(A1F, p1b),
                                           __fmul_rn(A2F, p2b)), d1);
            sp[t * HID + k0] = pa;
            sp[t * HID + k1] = pb;
            p2a = p1a; p1a = pa;
            p2b = p1b; p1b = pb;
        }
    }
    __syncthreads();

    {
        const int jg = tid >> 7;
        const int t  = tid & 127;
        if (t < TLEN) {
            const float* pr = sp + t * HID;
            const float* wb = sw + jg * 5 * HID;
            float a0 = 0.f, a1 = 0.f, a2 = 0.f, a3 = 0.f, a4 = 0.f;
            #pragma unroll 5
            for (int k = 0; k < HID; k += 4) {
                float4 pv = *(const float4*)(pr + k);
                float4 q0 = *(const float4*)(wb + 0 * HID + k);
                float4 q1 = *(const float4*)(wb + 1 * HID + k);
                float4 q2 = *(const float4*)(wb + 2 * HID + k);
                float4 q3 = *(const float4*)(wb + 3 * HID + k);
                float4 q4 = *(const float4*)(wb + 4 * HID + k);
                a0 = __fmaf_rn(pv.x, q0.x, a0); a0 = __fmaf_rn(pv.y, q0.y, a0);
                a0 = __fmaf_rn(pv.z, q0.z, a0); a0 = __fmaf_rn(pv.w, q0.w, a0);
                a1 = __fmaf_rn(pv.x, q1.x, a1); a1 = __fmaf_rn(pv.y, q1.y, a1);
                a1 = __fmaf_rn(pv.z, q1.z, a1); a1 = __fmaf_rn(pv.w, q1.w, a1);
                a2 = __fmaf_rn(pv.x, q2.x, a2); a2 = __fmaf_rn(pv.y, q2.y, a2);
                a2 = __fmaf_rn(pv.z, q2.z, a2); a2 = __fmaf_rn(pv.w, q2.w, a2);
                a3 = __fmaf_rn(pv.x, q3.x, a3); a3 = __fmaf_rn(pv.y, q3.y, a3);
                a3 = __fmaf_rn(pv.z, q3.z, a3); a3 = __fmaf_rn(pv.w, q3.w, a3);
                a4 = __fmaf_rn(pv.x, q4.x, a4); a4 = __fmaf_rn(pv.y, q4.y, a4);
                a4 = __fmaf_rn(pv.z, q4.z, a4); a4 = __fmaf_rn(pv.w, q4.w, a4);
            }
            float* scr = sc + t * NOUT + jg * 5;
            scr[0] = a0; scr[1] = a1; scr[2] = a2; scr[3] = a3; scr[4] = a4;
        }
    }
    __syncthreads();

    if (tid < NOUT) {
        float bb = b3[tid];
        float v = 0.f, s = 0.f;
        float* spk = sp + tid * TLEN;
        for (int t = 0; t < TLEN; t++) {
            float cur = __fadd_rn(sc[t * NOUT + tid], bb);
            float t1  = __fmul_rn(SGF, v);
            float t2  = __fmul_rn(t1, __fsub_rn(1.f, s));
            float vn  = __fadd_rn(t2, cur);
            s = (vn >= 1.f) ? 1.f : 0.f;
            v = vn;
            spk[t] = s;
        }
    }
    __syncthreads();

    float* ob = out + (size_t)b * (NOUT * TLEN);
    for (int i = tid; i < NOUT * TLEN; i += 256) ob[i] = sp[i];
}

#define SCAN_SMEM ((TLEN * HID + NOUT * HID + TLEN * NOUT) * (int)sizeof(float))

extern "C" void kernel_launch(void* const* d_in, const int* in_sizes, int n_in,
                              void* d_out, int out_size)
{
    const float* inputs = (const float*)d_in[0];  // [1024, 784]
    const float* w1     = (const float*)d_in[1];  // [500, 784]
    const float* b1     = (const float*)d_in[2];  // [500]
    const float* w2     = (const float*)d_in[3];  // [500, 500]
    const float* b2     = (const float*)d_in[4];  // [500]
    const float* w3     = (const float*)d_in[5];  // [10, 500]
    const float* b3     = (const float*)d_in[6];  // [10]
    float* out          = (float*)d_out;          // [1024, 10, 100]

    float* h_buf;
    float* drive_buf;
    cudaGetSymbolAddress((void**)&h_buf, g_h);
    cudaGetSymbolAddress((void**)&drive_buf, g_drive);

    cudaFuncSetAttribute(scan_kernel,
                         cudaFuncAttributeMaxDynamicSharedMemorySize, SCAN_SMEM);

    dim3 blk(128);
    dim3 grd((HID + BN - 1) / BN, BATCH / BM);   // 16 x 16 = 256 blocks
    gemm_bias_act<0><<<grd, blk>>>(inputs, w1, b1, h_buf, BATCH, HID, NIN);
    gemm_bias_act<1><<<grd, blk>>>(h_buf, w2, b2, drive_buf, BATCH, HID, HID);
    scan_kernel<<<BATCH, 256, SCAN_SMEM>>>(w3, b3, out);
}